// round 16
// baseline (speedup 1.0000x reference)
#include <cuda_runtime.h>
#include <cuda_bf16.h>

// WeightedAverage: out = sum_{3x3} v*exp(-v) / sum_{3x3} exp(-v)
// (softmax(-(local - x^2)) == softmax(-local); zero padding == OOB v=0.)
//
// R15 base (best 52.3us: tiles 128x512, 8 warps x 64 rows, grid 576 single
// wave, __ldcs/__stcs, 3-slot ring prefetched 2 rows ahead, fully unrolled)
// with halo terms obtained by SHUFFLING THE COMPUTED (w, wv) of the
// neighbor lane instead of recomputing exp: exps 1.5 -> 1.0 per pixel,
// all-lane halo LDGs eliminated (slot = {float4, edge}). Unlike failed R13,
// the shfl here runs AFTER/parallel-to the exps, not ahead of them.

#define IMG_W   1536
#define IMG_H   1536
#define SROWS   64
#define WPB     8
#define TILES_X 12
#define TILES_Y 3
#define N_IMG   16
#define NBLK    (TILES_X * TILES_Y * N_IMG)   // 576 = one tile per block

struct Slot { float4 v; float edge; };

__device__ __forceinline__ float4 f4add(const float4 a, const float4 b) {
    return make_float4(a.x + b.x, a.y + b.y, a.z + b.z, a.w + b.w);
}

__global__ __launch_bounds__(256, 4)
void wavg_kernel(const float* __restrict__ x, float* __restrict__ out) {
    const int lane = threadIdx.x & 31;
    const int wrp  = threadIdx.x >> 5;

    const int t     = blockIdx.x;
    const int img_i = t / (TILES_X * TILES_Y);
    const int rem   = t - img_i * (TILES_X * TILES_Y);
    const int ty    = rem / TILES_X;
    const int tx    = rem - ty * TILES_X;

    const int col0 = tx * 128 + lane * 4;
    const int y0   = ty * (WPB * SROWS) + wrp * SROWS;
    const size_t ibase = (size_t)img_i * (size_t)(IMG_W * IMG_H);
    const float* __restrict__ img = x + ibase;
    float* __restrict__ optr = out + ibase + (size_t)y0 * IMG_W + col0;

    const bool has_l = (col0 > 0);
    const bool has_r = (col0 + 4 < IMG_W);

    Slot ring[3];

    // Load row y: streaming float4 + one predicated edge scalar (lanes 0/31).
    auto loadrow = [&](int y) -> Slot {
        Slot s;
        s.v = make_float4(0.f, 0.f, 0.f, 0.f);
        s.edge = 0.f;
        if ((unsigned)y < (unsigned)IMG_H) {
            const float* p = img + (size_t)y * IMG_W + col0;
            s.v = __ldcs(reinterpret_cast<const float4*>(p));
            if (lane == 0) {
                if (has_l) s.edge = __ldg(p - 1);
            } else if (lane == 31) {
                if (has_r) s.edge = __ldg(p + 4);
            }
        }
        return s;
    };

    // Horizontal 3-sums of w=exp(-v), wv=w*v. Halo terms are the COMPUTED
    // (w, wv) of the neighbor lane via shfl; edge lanes do one extra exp.
    auto hsum = [&](const Slot& s, float4& w, float4& wv) {
        const float w0 = __expf(-s.v.x);
        const float w1 = __expf(-s.v.y);
        const float w2 = __expf(-s.v.z);
        const float w3 = __expf(-s.v.w);
        const float a0 = w0 * s.v.x, a1 = w1 * s.v.y;
        const float a2 = w2 * s.v.z, a3 = w3 * s.v.w;

        float wl = __shfl_up_sync(0xffffffffu,  w3, 1);
        float al = __shfl_up_sync(0xffffffffu,  a3, 1);
        float wr = __shfl_down_sync(0xffffffffu, w0, 1);
        float ar = __shfl_down_sync(0xffffffffu, a0, 1);
        if (lane == 0) {
            const float we = __expf(-s.edge);    // edge=0 when OOB -> w=1, a=0
            wl = we; al = we * s.edge;
        } else if (lane == 31) {
            const float we = __expf(-s.edge);
            wr = we; ar = we * s.edge;
        }

        w.x = wl + w0 + w1;
        w.y = w0 + w1 + w2;
        w.z = w1 + w2 + w3;
        w.w = w2 + w3 + wr;
        wv.x = al + a0 + a1;
        wv.y = a0 + a1 + a2;
        wv.z = a1 + a2 + a3;
        wv.w = a2 + a3 + ar;
    };

    // Prologue. slot(row) = (row - y0 + 2) % 3.
    Slot s_m1 = loadrow(y0 - 1);
    Slot s_0  = loadrow(y0);
    ring[0] = loadrow(y0 + 1);   // row y0+1 -> slot 0
    ring[1] = loadrow(y0 + 2);   // row y0+2 -> slot 1

    float4 hw0, hv0, hw1, hv1;
    hsum(s_m1, hw0, hv0);
    hsum(s_0,  hw1, hv1);
    float4 Aw  = f4add(hw0, hw1), Bw  = hw1;   // A = h(-1)+h(0), B = h(0)
    float4 Awv = f4add(hv0, hv1), Bwv = hv1;

    #pragma unroll
    for (int k = 0; k < SROWS; k++) {
        // Prefetch row y0+k+3 into slot (k+2)%3 (freed: row y0+k consumed
        // at k-1). Live rows k+1..k+3 occupy the 3 slots.
        if (k < SROWS - 2)
            ring[(k + 2) % 3] = loadrow(y0 + k + 3);
        // Consume row y0+k+1 (slot k%3), loaded 2 iterations ago.
        float4 hw, hv;
        hsum(ring[k % 3], hw, hv);

        const float4 den = f4add(Aw,  hw);
        const float4 num = f4add(Awv, hv);
        float4 o;
        o.x = __fdividef(num.x, den.x);
        o.y = __fdividef(num.y, den.y);
        o.z = __fdividef(num.z, den.z);
        o.w = __fdividef(num.w, den.w);
        __stcs(reinterpret_cast<float4*>(optr), o);
        optr += IMG_W;

        Aw  = f4add(Bw,  hw);  Bw  = hw;
        Awv = f4add(Bwv, hv);  Bwv = hv;
    }
}

extern "C" void kernel_launch(void* const* d_in, const int* in_sizes, int n_in,
                              void* d_out, int out_size) {
    const float* x = (const float*)d_in[0];
    float* out = (float*)d_out;
    wavg_kernel<<<NBLK, WPB * 32>>>(x, out);
}

// round 17
// speedup vs baseline: 1.0628x; 1.0628x over previous
#include <cuda_runtime.h>
#include <cuda_bf16.h>

// WeightedAverage: out = sum_{3x3} v*exp(-v) / sum_{3x3} exp(-v)
// (softmax(-(local - x^2)) == softmax(-local); zero padding == OOB v=0.)
//
// R15 base (best 52.3us: tiles 128x512 = 8 warps x 64 rows, grid 576 single
// wave, __ldcs streaming loads + __stcs stores, fully unrolled sweep, no
// shfl anywhere — R2/R13/R16 all proved shfl loses here) with prefetch
// distance 3: 4-slot ring, vectors float4 + halos packed float2.
// Gentle reg squeeze (~68 natural -> 64 cap), NOT an R9-style crush.

#define IMG_W   1536
#define IMG_H   1536
#define SROWS   64
#define WPB     8
#define TILES_X 12
#define TILES_Y 3
#define N_IMG   16
#define NBLK    (TILES_X * TILES_Y * N_IMG)   // 576 = one tile per block

__device__ __forceinline__ float4 f4add(const float4 a, const float4 b) {
    return make_float4(a.x + b.x, a.y + b.y, a.z + b.z, a.w + b.w);
}

__global__ __launch_bounds__(256, 4)
void wavg_kernel(const float* __restrict__ x, float* __restrict__ out) {
    const int lane = threadIdx.x & 31;
    const int wrp  = threadIdx.x >> 5;

    const int t     = blockIdx.x;
    const int img_i = t / (TILES_X * TILES_Y);
    const int rem   = t - img_i * (TILES_X * TILES_Y);
    const int ty    = rem / TILES_X;
    const int tx    = rem - ty * TILES_X;

    const int col0 = tx * 128 + lane * 4;
    const int y0   = ty * (WPB * SROWS) + wrp * SROWS;
    const size_t ibase = (size_t)img_i * (size_t)(IMG_W * IMG_H);
    const float* __restrict__ img = x + ibase;
    float* __restrict__ optr = out + ibase + (size_t)y0 * IMG_W + col0;

    const bool has_l = (col0 > 0);
    const bool has_r = (col0 + 4 < IMG_W);

    float4 rv[4];    // vector ring
    float2 rh[4];    // halo ring: {vl, vr}

    // Load row y into ring slot s: streaming float4 + both halo scalars.
    auto loadrow = [&](int y, int s) {
        float4 v = make_float4(0.f, 0.f, 0.f, 0.f);
        float vl = 0.f, vr = 0.f;
        if ((unsigned)y < (unsigned)IMG_H) {
            const float* p = img + (size_t)y * IMG_W + col0;
            v = __ldcs(reinterpret_cast<const float4*>(p));
            if (has_l) vl = __ldg(p - 1);
            if (has_r) vr = __ldg(p + 4);
        }
        rv[s] = v;
        rh[s] = make_float2(vl, vr);
    };

    // Horizontal 3-sums of w=exp(-v) and wv for ring slot s (pure compute).
    auto hsum = [&](int s, float4& w, float4& wv) {
        const float4 v = rv[s];
        const float vl = rh[s].x, vr = rh[s].y;
        const float w0 = __expf(-v.x);
        const float w1 = __expf(-v.y);
        const float w2 = __expf(-v.z);
        const float w3 = __expf(-v.w);
        const float wl = __expf(-vl);
        const float wr = __expf(-vr);
        w.x = wl + w0 + w1;
        w.y = w0 + w1 + w2;
        w.z = w1 + w2 + w3;
        w.w = w2 + w3 + wr;
        const float al = wl * vl, a0 = w0 * v.x, a1 = w1 * v.y;
        const float a2 = w2 * v.z, a3 = w3 * v.w, ar = wr * vr;
        wv.x = al + a0 + a1;
        wv.y = a0 + a1 + a2;
        wv.z = a1 + a2 + a3;
        wv.w = a2 + a3 + ar;
    };

    // Prologue. slot(row) = (row - y0 + 1) & 3.
    loadrow(y0 - 1, 0);
    loadrow(y0,     1);
    loadrow(y0 + 1, 2);
    loadrow(y0 + 2, 3);

    float4 hw0, hv0, hw1, hv1;
    hsum(0, hw0, hv0);           // row y0-1 (frees slot 0)
    hsum(1, hw1, hv1);           // row y0   (frees slot 1)
    float4 Aw  = f4add(hw0, hw1), Bw  = hw1;   // A = h(-1)+h(0), B = h(0)
    float4 Awv = f4add(hv0, hv1), Bwv = hv1;

    loadrow(y0 + 3, 0);          // refill freed slot 0 -> 3 rows in flight

    #pragma unroll
    for (int k = 0; k < SROWS; k++) {
        // Prefetch row y0+k+4 into slot (k+1)&3 (row y0+k, consumed at k-1).
        if (k < SROWS - 3)
            loadrow(y0 + k + 4, (k + 1) & 3);
        // Consume row y0+k+1 (slot (k+2)&3), loaded 3 iterations ago.
        float4 hw, hv;
        hsum((k + 2) & 3, hw, hv);

        const float4 den = f4add(Aw,  hw);
        const float4 num = f4add(Awv, hv);
        float4 o;
        o.x = __fdividef(num.x, den.x);
        o.y = __fdividef(num.y, den.y);
        o.z = __fdividef(num.z, den.z);
        o.w = __fdividef(num.w, den.w);
        __stcs(reinterpret_cast<float4*>(optr), o);
        optr += IMG_W;

        Aw  = f4add(Bw,  hw);  Bw  = hw;
        Awv = f4add(Bwv, hv);  Bwv = hv;
    }
}

extern "C" void kernel_launch(void* const* d_in, const int* in_sizes, int n_in,
                              void* d_out, int out_size) {
    const float* x = (const float*)d_in[0];
    float* out = (float*)d_out;
    wavg_kernel<<<NBLK, WPB * 32>>>(x, out);
}